// round 14
// baseline (speedup 1.0000x reference)
#include <cuda_runtime.h>
#include <cstdint>

// Channel-group winner-take-all, group size 4, NCHW fp32.
// x: [B, C, H, W] = [32, 512, 56, 56]. For each (b, cg, h, w) the group is the
// 4 consecutive channels {4cg..4cg+3}; keep elements equal to the group max,
// zero the rest.
//
// FINAL — triple-confirmed converged kernel:
//   R1  57.50us ncu / DRAM 76.1% / 6220 GB/s
//   R10 57.76us / 75.7% / 6188 GB/s
//   R13 57.86us / 75.8% / 6197 GB/s
// Session evidence (ncu dur):
//   R1/R10/R13  one-shot, block=256   57.5-57.9us  <- best, reproducible
//   R7          one-shot, block=512   57.98us  (neutral)
//   R9          collapsed index math  58.72us  (noise band)
//   R2          ILP=2 + __ldcs/__stcs 58.78us  (regs 40 -> occ 62%, negative)
//   R4          persistent grid       62.24us  (serialized stream, negative)
// Verdict: DRAM-bound at the ~6.2 TB/s mixed read/write stream ceiling
// (77.5% of 8 TB/s read-spec; gap = R/W bus turnaround). Traffic (411 MB)
// is information-theoretically minimal; fma/alu/L1/L2/issue all have >=2x
// headroom. Design space bracketed and closed — no further lever exists.

#define GB  32
#define GC  512
#define GHW (56 * 56)          // 3136, divisible by 4
#define GRP 4
#define HW4 (GHW / 4)          // 784 float4 chunks per plane
#define NCG (GC / GRP)         // 128 channel groups
#define NTHREADS_TOTAL (GB * NCG * HW4)   // 3,211,264

__global__ __launch_bounds__(256) void cgm_wta_kernel(
    const float4* __restrict__ x, float4* __restrict__ out)
{
    int tid = blockIdx.x * blockDim.x + threadIdx.x;
    if (tid >= NTHREADS_TOTAL) return;

    // Decompose tid -> (b, cg, p)
    int p  = tid % HW4;
    int t2 = tid / HW4;
    int cg = t2 % NCG;
    int b  = t2 / NCG;

    // float4 index of channel (4*cg) plane, chunk p
    long base = (long)b * (GC * (GHW / 4)) + (long)(cg * GRP) * (GHW / 4) + p;
    const int plane4 = GHW / 4;   // float4 stride between channel planes

    float4 v0 = x[base];
    float4 v1 = x[base + plane4];
    float4 v2 = x[base + 2 * plane4];
    float4 v3 = x[base + 3 * plane4];

    float4 m;
    m.x = fmaxf(fmaxf(v0.x, v1.x), fmaxf(v2.x, v3.x));
    m.y = fmaxf(fmaxf(v0.y, v1.y), fmaxf(v2.y, v3.y));
    m.z = fmaxf(fmaxf(v0.z, v1.z), fmaxf(v2.z, v3.z));
    m.w = fmaxf(fmaxf(v0.w, v1.w), fmaxf(v2.w, v3.w));

    float4 o0, o1, o2, o3;
    o0.x = (v0.x == m.x) ? v0.x : 0.0f;
    o0.y = (v0.y == m.y) ? v0.y : 0.0f;
    o0.z = (v0.z == m.z) ? v0.z : 0.0f;
    o0.w = (v0.w == m.w) ? v0.w : 0.0f;

    o1.x = (v1.x == m.x) ? v1.x : 0.0f;
    o1.y = (v1.y == m.y) ? v1.y : 0.0f;
    o1.z = (v1.z == m.z) ? v1.z : 0.0f;
    o1.w = (v1.w == m.w) ? v1.w : 0.0f;

    o2.x = (v2.x == m.x) ? v2.x : 0.0f;
    o2.y = (v2.y == m.y) ? v2.y : 0.0f;
    o2.z = (v2.z == m.z) ? v2.z : 0.0f;
    o2.w = (v2.w == m.w) ? v2.w : 0.0f;

    o3.x = (v3.x == m.x) ? v3.x : 0.0f;
    o3.y = (v3.y == m.y) ? v3.y : 0.0f;
    o3.z = (v3.z == m.z) ? v3.z : 0.0f;
    o3.w = (v3.w == m.w) ? v3.w : 0.0f;

    out[base]              = o0;
    out[base + plane4]     = o1;
    out[base + 2 * plane4] = o2;
    out[base + 3 * plane4] = o3;
}

extern "C" void kernel_launch(void* const* d_in, const int* in_sizes, int n_in,
                              void* d_out, int out_size)
{
    const float4* x   = (const float4*)d_in[0];
    float4*       out = (float4*)d_out;

    const int threads = 256;
    const int blocks  = (NTHREADS_TOTAL + threads - 1) / threads;  // 12544
    cgm_wta_kernel<<<blocks, threads>>>(x, out);
}

// round 15
// speedup vs baseline: 1.0054x; 1.0054x over previous
#include <cuda_runtime.h>
#include <cstdint>

// Channel-group winner-take-all, group size 4, NCHW fp32.
// x: [B, C, H, W] = [32, 512, 56, 56]. For each (b, cg, h, w) the group is the
// 4 consecutive channels {4cg..4cg+3}; keep elements equal to the group max,
// zero the rest.
//
// FINAL — triple-confirmed converged kernel:
//   R1  57.50us ncu / DRAM 76.1% / 6220 GB/s
//   R10 57.76us / 75.7% / 6188 GB/s
//   R13 57.86us / 75.8% / 6197 GB/s
// Session evidence (ncu dur):
//   R1/R10/R13  one-shot, block=256   57.5-57.9us  <- best, reproducible
//   R7          one-shot, block=512   57.98us  (neutral)
//   R9          collapsed index math  58.72us  (noise band)
//   R2          ILP=2 + __ldcs/__stcs 58.78us  (regs 40 -> occ 62%, negative)
//   R4          persistent grid       62.24us  (serialized stream, negative)
// Verdict: DRAM-bound at the ~6.2 TB/s mixed read/write stream ceiling
// (77.5% of 8 TB/s read-spec; gap = R/W bus turnaround). Traffic (411 MB)
// is information-theoretically minimal; fma/alu/L1/L2/issue all have >=2x
// headroom. Design space bracketed and closed — no further lever exists.

#define GB  32
#define GC  512
#define GHW (56 * 56)          // 3136, divisible by 4
#define GRP 4
#define HW4 (GHW / 4)          // 784 float4 chunks per plane
#define NCG (GC / GRP)         // 128 channel groups
#define NTHREADS_TOTAL (GB * NCG * HW4)   // 3,211,264

__global__ __launch_bounds__(256) void cgm_wta_kernel(
    const float4* __restrict__ x, float4* __restrict__ out)
{
    int tid = blockIdx.x * blockDim.x + threadIdx.x;
    if (tid >= NTHREADS_TOTAL) return;

    // Decompose tid -> (b, cg, p)
    int p  = tid % HW4;
    int t2 = tid / HW4;
    int cg = t2 % NCG;
    int b  = t2 / NCG;

    // float4 index of channel (4*cg) plane, chunk p
    long base = (long)b * (GC * (GHW / 4)) + (long)(cg * GRP) * (GHW / 4) + p;
    const int plane4 = GHW / 4;   // float4 stride between channel planes

    float4 v0 = x[base];
    float4 v1 = x[base + plane4];
    float4 v2 = x[base + 2 * plane4];
    float4 v3 = x[base + 3 * plane4];

    float4 m;
    m.x = fmaxf(fmaxf(v0.x, v1.x), fmaxf(v2.x, v3.x));
    m.y = fmaxf(fmaxf(v0.y, v1.y), fmaxf(v2.y, v3.y));
    m.z = fmaxf(fmaxf(v0.z, v1.z), fmaxf(v2.z, v3.z));
    m.w = fmaxf(fmaxf(v0.w, v1.w), fmaxf(v2.w, v3.w));

    float4 o0, o1, o2, o3;
    o0.x = (v0.x == m.x) ? v0.x : 0.0f;
    o0.y = (v0.y == m.y) ? v0.y : 0.0f;
    o0.z = (v0.z == m.z) ? v0.z : 0.0f;
    o0.w = (v0.w == m.w) ? v0.w : 0.0f;

    o1.x = (v1.x == m.x) ? v1.x : 0.0f;
    o1.y = (v1.y == m.y) ? v1.y : 0.0f;
    o1.z = (v1.z == m.z) ? v1.z : 0.0f;
    o1.w = (v1.w == m.w) ? v1.w : 0.0f;

    o2.x = (v2.x == m.x) ? v2.x : 0.0f;
    o2.y = (v2.y == m.y) ? v2.y : 0.0f;
    o2.z = (v2.z == m.z) ? v2.z : 0.0f;
    o2.w = (v2.w == m.w) ? v2.w : 0.0f;

    o3.x = (v3.x == m.x) ? v3.x : 0.0f;
    o3.y = (v3.y == m.y) ? v3.y : 0.0f;
    o3.z = (v3.z == m.z) ? v3.z : 0.0f;
    o3.w = (v3.w == m.w) ? v3.w : 0.0f;

    out[base]              = o0;
    out[base + plane4]     = o1;
    out[base + 2 * plane4] = o2;
    out[base + 3 * plane4] = o3;
}

extern "C" void kernel_launch(void* const* d_in, const int* in_sizes, int n_in,
                              void* d_out, int out_size)
{
    const float4* x   = (const float4*)d_in[0];
    float4*       out = (float4*)d_out;

    const int threads = 256;
    const int blocks  = (NTHREADS_TOTAL + threads - 1) / threads;  // 12544
    cgm_wta_kernel<<<blocks, threads>>>(x, out);
}